// round 2
// baseline (speedup 1.0000x reference)
#include <cuda_runtime.h>

#define BATCHN 2048
#define SEQN   128
#define FDIM   512
#define NACT   128
#define GN_EPS 1e-5f

// ---------------- scratch (device globals; no allocation allowed) ----------
__device__ float g_avg[2][BATCHN * FDIM];   // post-GN masked means (p, e)
__device__ float g_pembed[BATCHN * FDIM];   // p_embed
__device__ int   g_counts[NACT];
__device__ int   g_offsets[NACT];
__device__ int   g_cursor[NACT];
__device__ int   g_order[BATCHN];

// ---------------- stage 1: masked mean over SEQ + GroupNorm(1,1) ----------
// grid (BATCHN, 2) ; 128 threads; thread = one float4 feature column
__global__ __launch_bounds__(128) void mean_gn_kernel(
    const float* __restrict__ pre, const float* __restrict__ eff,
    const float* __restrict__ gamma, const float* __restrict__ beta)
{
    int b = blockIdx.x, t = blockIdx.y;
    const float* src = (t == 0 ? pre : eff) + (size_t)b * SEQN * FDIM;
    const float4* p4 = (const float4*)src;
    int tid = threadIdx.x;

    float sx = 0.f, sy = 0.f, sz = 0.f, sw = 0.f;
    float cx = 0.f, cy = 0.f, cz = 0.f, cw = 0.f;
#pragma unroll 4
    for (int s = 0; s < SEQN; s++) {
        float4 v = p4[s * (FDIM / 4) + tid];
        sx += v.x; sy += v.y; sz += v.z; sw += v.w;
        cx += (v.x != 0.f); cy += (v.y != 0.f);
        cz += (v.z != 0.f); cw += (v.w != 0.f);
    }
    float yx = sx / cx, yy = sy / cy, yz = sz / cz, yw = sw / cw;

    float ls  = yx + yy + yz + yw;
    float ls2 = yx * yx + yy * yy + yz * yz + yw * yw;
#pragma unroll
    for (int o = 16; o > 0; o >>= 1) {
        ls  += __shfl_xor_sync(0xffffffffu, ls,  o);
        ls2 += __shfl_xor_sync(0xffffffffu, ls2, o);
    }
    __shared__ float ss[4], ss2[4];
    int w = tid >> 5, l = tid & 31;
    if (l == 0) { ss[w] = ls; ss2[w] = ls2; }
    __syncthreads();
    float S  = ss[0] + ss[1] + ss[2] + ss[3];
    float S2 = ss2[0] + ss2[1] + ss2[2] + ss2[3];

    float mean = S * (1.f / FDIM);
    float var  = S2 * (1.f / FDIM) - mean * mean;
    float inv  = rsqrtf(var + GN_EPS);
    float g = gamma[0] * inv, be = beta[0];

    float4 o;
    o.x = (yx - mean) * g + be;
    o.y = (yy - mean) * g + be;
    o.z = (yz - mean) * g + be;
    o.w = (yw - mean) * g + be;
    ((float4*)&g_avg[t][(size_t)b * FDIM])[tid] = o;
}

// ---------------- action sort: hist / scan / scatter ----------------------
__global__ void zero_kernel() {
    int tid = threadIdx.x;
    if (tid < NACT) g_counts[tid] = 0;
}
__global__ void hist_kernel(const int* __restrict__ action) {
    int b = blockIdx.x * blockDim.x + threadIdx.x;
    if (b < BATCHN) atomicAdd(&g_counts[action[b]], 1);
}
__global__ void scan_kernel() {
    __shared__ int s[NACT];
    int tid = threadIdx.x;
    s[tid] = g_counts[tid];
    __syncthreads();
    for (int off = 1; off < NACT; off <<= 1) {
        int v = (tid >= off) ? s[tid - off] : 0;
        __syncthreads();
        s[tid] += v;
        __syncthreads();
    }
    int excl = s[tid] - g_counts[tid];
    g_offsets[tid] = excl;
    g_cursor[tid]  = excl;
}
__global__ void scatter_kernel(const int* __restrict__ action) {
    int b = blockIdx.x * blockDim.x + threadIdx.x;
    if (b < BATCHN) {
        int pos = atomicAdd(&g_cursor[action[b]], 1);
        g_order[pos] = b;
    }
}

// ---------------- stage 2: embed GEMMs  C[m,n] = sum_k A[m,k]*Bw[n,k]+bias -
// grid (32, 8, 2) ; 256 threads ; 64x64 tile, K-tile 32, 4x4 micro-tile
__global__ __launch_bounds__(256) void embed_gemm_kernel(
    const float* __restrict__ pw, const float* __restrict__ pb,
    const float* __restrict__ ew, const float* __restrict__ eb,
    float* __restrict__ out)
{
    int t = blockIdx.z;
    const float* A    = g_avg[t];
    const float* Bw   = t ? ew : pw;
    const float* bias = t ? eb : pb;
    float* C = t ? (out + (size_t)BATCHN * FDIM) : g_pembed;

    int m0 = blockIdx.x * 64, n0 = blockIdx.y * 64;
    __shared__ float As[32][68];   // [k][m] transposed, stride 68 keeps 16B align
    __shared__ float Bs[32][68];

    int tid = threadIdx.x;
    int ty = tid >> 4, tx = tid & 15;   // 16x16 threads of 4x4 outputs
    float acc[4][4] = {};

    for (int kt = 0; kt < FDIM; kt += 32) {
#pragma unroll
        for (int i = 0; i < 2; i++) {
            int idx = i * 256 + tid;
            int m = idx >> 3, kq = idx & 7;
            float4 va = *(const float4*)&A[(size_t)(m0 + m) * FDIM + kt + kq * 4];
            As[kq * 4 + 0][m] = va.x; As[kq * 4 + 1][m] = va.y;
            As[kq * 4 + 2][m] = va.z; As[kq * 4 + 3][m] = va.w;
            float4 vb = *(const float4*)&Bw[(size_t)(n0 + m) * FDIM + kt + kq * 4];
            Bs[kq * 4 + 0][m] = vb.x; Bs[kq * 4 + 1][m] = vb.y;
            Bs[kq * 4 + 2][m] = vb.z; Bs[kq * 4 + 3][m] = vb.w;
        }
        __syncthreads();
#pragma unroll
        for (int k = 0; k < 32; k++) {
            float4 a4 = *(const float4*)&As[k][ty * 4];
            float4 b4 = *(const float4*)&Bs[k][tx * 4];
            float av[4] = {a4.x, a4.y, a4.z, a4.w};
            float bv[4] = {b4.x, b4.y, b4.z, b4.w};
#pragma unroll
            for (int i = 0; i < 4; i++)
#pragma unroll
                for (int j = 0; j < 4; j++)
                    acc[i][j] += av[i] * bv[j];
        }
        __syncthreads();
    }

    float4 bia = *(const float4*)&bias[n0 + tx * 4];
#pragma unroll
    for (int i = 0; i < 4; i++) {
        float4 o;
        o.x = acc[i][0] + bia.x; o.y = acc[i][1] + bia.y;
        o.z = acc[i][2] + bia.z; o.w = acc[i][3] + bia.w;
        *(float4*)&C[(size_t)(m0 + ty * 4 + i) * FDIM + n0 + tx * 4] = o;
    }
}

// ---------------- stage 3: grouped matvec  out[b,i] = W[a][i,:] . p_embed[b]
// grid (NACT, 4) ; 256 threads ; 128 W-rows x 32 batches, K-tile 32
__global__ __launch_bounds__(256) void matvec_kernel(
    const float* __restrict__ W, float* __restrict__ out)
{
    int act = blockIdx.x, rt = blockIdx.y;
    int cnt = g_counts[act];
    if (cnt == 0) return;
    int start = g_offsets[act];
    const float* Wa = W + (size_t)act * FDIM * FDIM + (size_t)rt * 128 * FDIM;

    __shared__ float Ws[32][132];  // [k][row], stride 132 -> 16B aligned rows
    __shared__ float Es[32][36];   // [k][batch]
    __shared__ int   sb[32];

    int tid = threadIdx.x;
    int ty = tid >> 3, tx = tid & 7;   // 32 row groups x 8 batch groups

    for (int c0 = 0; c0 < cnt; c0 += 32) {
        __syncthreads();
        if (tid < 32) {
            int gi = c0 + tid;
            sb[tid] = (gi < cnt) ? g_order[start + gi] : -1;
        }
        __syncthreads();

        float acc[4][4] = {};
        for (int kt = 0; kt < FDIM; kt += 32) {
#pragma unroll
            for (int i = 0; i < 4; i++) {
                int idx = i * 256 + tid;
                int r = idx >> 3, kq = idx & 7;
                float4 v = *(const float4*)&Wa[(size_t)r * FDIM + kt + kq * 4];
                Ws[kq * 4 + 0][r] = v.x; Ws[kq * 4 + 1][r] = v.y;
                Ws[kq * 4 + 2][r] = v.z; Ws[kq * 4 + 3][r] = v.w;
            }
            {
                int bI = tid >> 3, kq = tid & 7;
                int bb = sb[bI];
                float4 e = make_float4(0.f, 0.f, 0.f, 0.f);
                if (bb >= 0)
                    e = *(const float4*)&g_pembed[(size_t)bb * FDIM + kt + kq * 4];
                Es[kq * 4 + 0][bI] = e.x; Es[kq * 4 + 1][bI] = e.y;
                Es[kq * 4 + 2][bI] = e.z; Es[kq * 4 + 3][bI] = e.w;
            }
            __syncthreads();
#pragma unroll
            for (int k = 0; k < 32; k++) {
                float4 a4 = *(const float4*)&Ws[k][ty * 4];
                float4 e4 = *(const float4*)&Es[k][tx * 4];
                float av[4] = {a4.x, a4.y, a4.z, a4.w};
                float ev[4] = {e4.x, e4.y, e4.z, e4.w};
#pragma unroll
                for (int i = 0; i < 4; i++)
#pragma unroll
                    for (int j = 0; j < 4; j++)
                        acc[i][j] += av[i] * ev[j];
            }
            __syncthreads();
        }

#pragma unroll
        for (int j = 0; j < 4; j++) {
            int bb = sb[tx * 4 + j];
            if (bb >= 0) {
                float4 o = make_float4(acc[0][j], acc[1][j], acc[2][j], acc[3][j]);
                *(float4*)&out[(size_t)bb * FDIM + rt * 128 + ty * 4] = o;
            }
        }
    }
}

// ---------------- launch ---------------------------------------------------
extern "C" void kernel_launch(void* const* d_in, const int* in_sizes, int n_in,
                              void* d_out, int out_size)
{
    const float* pre    = (const float*)d_in[0];
    const float* eff    = (const float*)d_in[1];
    const int*   action = (const int*)  d_in[2];
    const float* W      = (const float*)d_in[3];
    const float* pw     = (const float*)d_in[4];
    const float* pb     = (const float*)d_in[5];
    const float* ew     = (const float*)d_in[6];
    const float* eb     = (const float*)d_in[7];
    const float* gamma  = (const float*)d_in[8];
    const float* beta   = (const float*)d_in[9];
    float* out = (float*)d_out;

    mean_gn_kernel<<<dim3(BATCHN, 2), 128>>>(pre, eff, gamma, beta);
    zero_kernel<<<1, 128>>>();
    hist_kernel<<<(BATCHN + 255) / 256, 256>>>(action);
    scan_kernel<<<1, NACT>>>();
    scatter_kernel<<<(BATCHN + 255) / 256, 256>>>(action);
    embed_gemm_kernel<<<dim3(32, 8, 2), 256>>>(pw, pb, ew, eb, out);
    matvec_kernel<<<dim3(NACT, 4), 256>>>(W, out);
}

// round 3
// speedup vs baseline: 1.0173x; 1.0173x over previous
#include <cuda_runtime.h>

#define BATCHN 2048
#define SEQN   128
#define FDIM   512
#define NACT   128
#define GN_EPS 1e-5f

typedef unsigned long long u64;

// ---- packed fp32x2 helpers (sm_103a FFMA2 path, 2x FFMA throughput) -------
__device__ __forceinline__ u64 pack_dup(float x) {
    u64 r; asm("mov.b64 %0, {%1, %1};" : "=l"(r) : "f"(x)); return r;
}
__device__ __forceinline__ void fma2(u64& d, u64 a, u64 b) {
    asm("fma.rn.f32x2 %0, %1, %2, %0;" : "+l"(d) : "l"(a), "l"(b));
}
__device__ __forceinline__ float2 unpack2(u64 v) {
    float lo, hi; asm("mov.b64 {%0, %1}, %2;" : "=f"(lo), "=f"(hi) : "l"(v));
    return make_float2(lo, hi);
}

// ---- scratch ---------------------------------------------------------------
__device__ float g_avg[2][BATCHN * FDIM];
__device__ float g_pembed[BATCHN * FDIM];
__device__ int   g_counts[NACT];
__device__ int   g_offsets[NACT];
__device__ int   g_order[BATCHN];

// ---- stage 1: masked mean + GroupNorm(1,1); block(0,0) also sorts actions -
__global__ __launch_bounds__(128) void mean_gn_sort_kernel(
    const float* __restrict__ pre, const float* __restrict__ eff,
    const float* __restrict__ gamma, const float* __restrict__ beta,
    const int* __restrict__ action)
{
    int b = blockIdx.x, t = blockIdx.y;
    const float4* p4 = (const float4*)((t == 0 ? pre : eff) + (size_t)b * SEQN * FDIM);
    int tid = threadIdx.x;

    float sx = 0.f, sy = 0.f, sz = 0.f, sw = 0.f;
    float cx = 0.f, cy = 0.f, cz = 0.f, cw = 0.f;
#pragma unroll 8
    for (int s = 0; s < SEQN; s++) {
        float4 v = p4[s * (FDIM / 4) + tid];
        sx += v.x; sy += v.y; sz += v.z; sw += v.w;
        cx += (v.x != 0.f); cy += (v.y != 0.f);
        cz += (v.z != 0.f); cw += (v.w != 0.f);
    }
    float yx = sx / cx, yy = sy / cy, yz = sz / cz, yw = sw / cw;

    float ls  = yx + yy + yz + yw;
    float ls2 = yx * yx + yy * yy + yz * yz + yw * yw;
#pragma unroll
    for (int o = 16; o > 0; o >>= 1) {
        ls  += __shfl_xor_sync(0xffffffffu, ls,  o);
        ls2 += __shfl_xor_sync(0xffffffffu, ls2, o);
    }
    __shared__ float ss[4], ss2[4];
    int w = tid >> 5, l = tid & 31;
    if (l == 0) { ss[w] = ls; ss2[w] = ls2; }
    __syncthreads();
    float S  = ss[0] + ss[1] + ss[2] + ss[3];
    float S2 = ss2[0] + ss2[1] + ss2[2] + ss2[3];

    float mean = S * (1.f / FDIM);
    float var  = S2 * (1.f / FDIM) - mean * mean;
    float inv  = rsqrtf(var + GN_EPS);
    float g = gamma[0] * inv, be = beta[0];

    float4 o;
    o.x = (yx - mean) * g + be;
    o.y = (yy - mean) * g + be;
    o.z = (yz - mean) * g + be;
    o.w = (yw - mean) * g + be;
    ((float4*)&g_avg[t][(size_t)b * FDIM])[tid] = o;

    // ---- folded action sort (runs in the shadow of the other 4095 blocks) -
    if (blockIdx.x == 0 && blockIdx.y == 0) {
        __shared__ int h[NACT], s[NACT], cur[NACT];
        h[tid] = 0;
        __syncthreads();
        for (int bb = tid; bb < BATCHN; bb += 128)
            atomicAdd(&h[action[bb]], 1);
        __syncthreads();
        int v = h[tid];
        s[tid] = v;
        __syncthreads();
        for (int off = 1; off < NACT; off <<= 1) {
            int t2 = (tid >= off) ? s[tid - off] : 0;
            __syncthreads();
            s[tid] += t2;
            __syncthreads();
        }
        int excl = s[tid] - v;
        g_counts[tid]  = v;
        g_offsets[tid] = excl;
        cur[tid] = excl;
        __syncthreads();
        for (int bb = tid; bb < BATCHN; bb += 128) {
            int pos = atomicAdd(&cur[action[bb]], 1);
            g_order[pos] = bb;
        }
    }
}

// ---- stage 2: embed GEMMs  C[m,n] = sum_k A[m,k]*Bw[n,k] + bias -----------
// grid (16,4,2), 256 thr, 128x128 tile, ktile 16, 8x8 micro via FFMA2
__global__ __launch_bounds__(256) void embed_gemm_kernel(
    const float* __restrict__ pw, const float* __restrict__ pb,
    const float* __restrict__ ew, const float* __restrict__ eb,
    float* __restrict__ out)
{
    int t = blockIdx.z;
    const float* A    = g_avg[t];
    const float* Bw   = t ? ew : pw;
    const float* bias = t ? eb : pb;
    float* C = t ? (out + (size_t)BATCHN * FDIM) : g_pembed;

    int m0 = blockIdx.x * 128, n0 = blockIdx.y * 128;
    __shared__ float As[16][132];   // [k][m]; 132*4=528 = 33*16 -> 16B aligned rows
    __shared__ float Bs[16][132];

    int tid = threadIdx.x;
    int ty = tid >> 4, tx = tid & 15;   // 16x16 threads, 8x8 outputs each

    u64 acc[4][8];
#pragma unroll
    for (int i = 0; i < 4; i++)
#pragma unroll
        for (int j = 0; j < 8; j++) acc[i][j] = 0ull;

    for (int kt = 0; kt < FDIM; kt += 16) {
#pragma unroll
        for (int i = 0; i < 2; i++) {
            int idx = i * 256 + tid;
            int m = idx >> 2, q = idx & 3;
            float4 va = *(const float4*)&A[(size_t)(m0 + m) * FDIM + kt + q * 4];
            As[q * 4 + 0][m] = va.x; As[q * 4 + 1][m] = va.y;
            As[q * 4 + 2][m] = va.z; As[q * 4 + 3][m] = va.w;
            float4 vb = *(const float4*)&Bw[(size_t)(n0 + m) * FDIM + kt + q * 4];
            Bs[q * 4 + 0][m] = vb.x; Bs[q * 4 + 1][m] = vb.y;
            Bs[q * 4 + 2][m] = vb.z; Bs[q * 4 + 3][m] = vb.w;
        }
        __syncthreads();
#pragma unroll
        for (int k = 0; k < 16; k++) {
            ulonglong2 a01 = *(const ulonglong2*)&As[k][ty * 8];
            ulonglong2 a23 = *(const ulonglong2*)&As[k][ty * 8 + 4];
            float4 b0 = *(const float4*)&Bs[k][tx * 8];
            float4 b1 = *(const float4*)&Bs[k][tx * 8 + 4];
            u64 av[4] = {a01.x, a01.y, a23.x, a23.y};
            u64 bd[8] = {pack_dup(b0.x), pack_dup(b0.y), pack_dup(b0.z), pack_dup(b0.w),
                         pack_dup(b1.x), pack_dup(b1.y), pack_dup(b1.z), pack_dup(b1.w)};
#pragma unroll
            for (int rp = 0; rp < 4; rp++)
#pragma unroll
                for (int j = 0; j < 8; j++)
                    fma2(acc[rp][j], av[rp], bd[j]);
        }
        __syncthreads();
    }

    float4 bi0 = *(const float4*)&bias[n0 + tx * 8];
    float4 bi1 = *(const float4*)&bias[n0 + tx * 8 + 4];
    float bb8[8] = {bi0.x, bi0.y, bi0.z, bi0.w, bi1.x, bi1.y, bi1.z, bi1.w};

#pragma unroll
    for (int rp = 0; rp < 4; rp++) {
        float lo[8], hi[8];
#pragma unroll
        for (int j = 0; j < 8; j++) {
            float2 p = unpack2(acc[rp][j]);
            lo[j] = p.x + bb8[j];
            hi[j] = p.y + bb8[j];
        }
        int r0 = m0 + ty * 8 + rp * 2;
        float* c0 = &C[(size_t)r0 * FDIM + n0 + tx * 8];
        float* c1 = &C[(size_t)(r0 + 1) * FDIM + n0 + tx * 8];
        *(float4*)c0       = make_float4(lo[0], lo[1], lo[2], lo[3]);
        *(float4*)(c0 + 4) = make_float4(lo[4], lo[5], lo[6], lo[7]);
        *(float4*)c1       = make_float4(hi[0], hi[1], hi[2], hi[3]);
        *(float4*)(c1 + 4) = make_float4(hi[4], hi[5], hi[6], hi[7]);
    }
}

// ---- stage 3: grouped matvec, 128 W-rows x 16 batches per block -----------
// grid (NACT, 4), 128 thr, ktile 16, 4x4 micro via FFMA2
__global__ __launch_bounds__(128) void matvec_kernel(
    const float* __restrict__ W, float* __restrict__ out)
{
    int act = blockIdx.x, rb = blockIdx.y;
    int cnt = g_counts[act];
    if (cnt == 0) return;
    int start = g_offsets[act];
    const float* Wa = W + (size_t)act * FDIM * FDIM + (size_t)rb * 128 * FDIM;

    __shared__ float Ws[16][132];
    __shared__ float Es[16][20];     // 20*4=80, multiple of 16 -> aligned
    __shared__ int   sb[16];

    int tid = threadIdx.x;
    int ty = tid >> 2, tx = tid & 3;  // 32 row-groups x 4 col-groups

    for (int c0 = 0; c0 < cnt; c0 += 16) {
        __syncthreads();
        if (tid < 16) {
            int gi = c0 + tid;
            sb[tid] = (gi < cnt) ? g_order[start + gi] : -1;
        }
        __syncthreads();

        u64 acc[2][4] = {{0ull,0ull,0ull,0ull},{0ull,0ull,0ull,0ull}};

        for (int kt = 0; kt < FDIM; kt += 16) {
#pragma unroll
            for (int i = 0; i < 4; i++) {
                int idx = i * 128 + tid;
                int m = idx >> 2, q = idx & 3;
                float4 v = *(const float4*)&Wa[(size_t)m * FDIM + kt + q * 4];
                Ws[q * 4 + 0][m] = v.x; Ws[q * 4 + 1][m] = v.y;
                Ws[q * 4 + 2][m] = v.z; Ws[q * 4 + 3][m] = v.w;
            }
            if (tid < 64) {
                int c = tid >> 2, q = tid & 3;
                int bb = sb[c];
                float4 e = make_float4(0.f, 0.f, 0.f, 0.f);
                if (bb >= 0)
                    e = *(const float4*)&g_pembed[(size_t)bb * FDIM + kt + q * 4];
                Es[q * 4 + 0][c] = e.x; Es[q * 4 + 1][c] = e.y;
                Es[q * 4 + 2][c] = e.z; Es[q * 4 + 3][c] = e.w;
            }
            __syncthreads();
#pragma unroll
            for (int k = 0; k < 16; k++) {
                ulonglong2 a = *(const ulonglong2*)&Ws[k][ty * 4];
                float4 b = *(const float4*)&Es[k][tx * 4];
                u64 bd[4] = {pack_dup(b.x), pack_dup(b.y), pack_dup(b.z), pack_dup(b.w)};
#pragma unroll
                for (int j = 0; j < 4; j++) {
                    fma2(acc[0][j], a.x, bd[j]);
                    fma2(acc[1][j], a.y, bd[j]);
                }
            }
            __syncthreads();
        }

#pragma unroll
        for (int j = 0; j < 4; j++) {
            int bb = sb[tx * 4 + j];
            if (bb >= 0) {
                float2 p0 = unpack2(acc[0][j]);
                float2 p1 = unpack2(acc[1][j]);
                *(float4*)&out[(size_t)bb * FDIM + rb * 128 + ty * 4] =
                    make_float4(p0.x, p0.y, p1.x, p1.y);
            }
        }
    }
}

// ---- launch ----------------------------------------------------------------
extern "C" void kernel_launch(void* const* d_in, const int* in_sizes, int n_in,
                              void* d_out, int out_size)
{
    const float* pre    = (const float*)d_in[0];
    const float* eff    = (const float*)d_in[1];
    const int*   action = (const int*)  d_in[2];
    const float* W      = (const float*)d_in[3];
    const float* pw     = (const float*)d_in[4];
    const float* pb     = (const float*)d_in[5];
    const float* ew     = (const float*)d_in[6];
    const float* eb     = (const float*)d_in[7];
    const float* gamma  = (const float*)d_in[8];
    const float* beta   = (const float*)d_in[9];
    float* out = (float*)d_out;

    mean_gn_sort_kernel<<<dim3(BATCHN, 2), 128>>>(pre, eff, gamma, beta, action);
    embed_gemm_kernel<<<dim3(16, 4, 2), 256>>>(pw, pb, ew, eb, out);
    matvec_kernel<<<dim3(NACT, 4), 128>>>(W, out);
}